// round 13
// baseline (speedup 1.0000x reference)
#include <cuda_runtime.h>
#include <cstdint>

constexpr int kB = 8, kN = 4096, kD = 1024, kNQ = 64;
constexpr int kTOPK = 1024;
constexpr int KC = 16;      // qw gemm K-chunk
constexpr int AP = 132;     // qw smem pitch (floats)
constexpr int STG = KC * AP;
constexpr int kSPLIT = 16;  // qw split-K

// scores: 128 threads, 8x8 thread tile, KC3=16 double-buffered
constexpr int KC3 = 16;
constexpr int AP3 = 132;               // A pitch (floats per k-row of 128 rows)
constexpr int BP3 = 128;               // B pitch (floats per k-row, dup chunks)
constexpr int ASTG = KC3 * AP3;        // 2112 floats
constexpr int BSTG = KC3 * BP3;        // 2048 floats
constexpr int SMEM_FLOATS = 2 * ASTG + 2 * BSTG;   // 8320 floats = 33280 B

// ---------------- scratch ----------------
__device__ float g_QW[kNQ * kD];            // (query_embed @ key_w^T) / 32
__device__ float g_QWp[kSPLIT * kNQ * kD];  // split-K partials
__device__ float g_qb[kNQ];                 // (query_embed @ key_b) / 32
__device__ float g_S[(size_t)kB * kNQ * kN];// scores [b][q][n]
__device__ float g_lse[kB * kNQ];           // logsumexp per (b,q)
__device__ float g_logit[kB * kN];          // max_q (s - lse) per token
__device__ int   g_idx[kB * kTOPK];         // selected indices, ascending

// ---------------- f32x2 helpers ----------------
__device__ __forceinline__ void f32x2_unpack(unsigned long long v, float& lo, float& hi) {
    asm("mov.b64 {%0, %1}, %2;" : "=f"(lo), "=f"(hi) : "l"(v));
}
__device__ __forceinline__ unsigned long long f32x2_fma(unsigned long long a,
                                                        unsigned long long b,
                                                        unsigned long long c) {
    unsigned long long d;
    asm("fma.rn.f32x2 %0, %1, %2, %3;" : "=l"(d) : "l"(a), "l"(b), "l"(c));
    return d;
}

// ================= fp32 tile GEMM, KC=16, 256 thr (qw only) =================
__device__ __forceinline__ void ldg_stage(const float* __restrict__ A,
                                          const float* __restrict__ Bm,
                                          int k0, float4 pa[2], float4& pb, int tid)
{
#pragma unroll
    for (int i = 0; i < 2; i++) {
        int idx = tid + i * 256;
        int r = idx >> 2, c4 = idx & 3;
        pa[i] = *(const float4*)(A + (size_t)r * kD + k0 + c4 * 4);
    }
    {
        int q = tid >> 2, c4 = tid & 3;
        pb = *(const float4*)(Bm + (size_t)q * kD + k0 + c4 * 4);
    }
}
__device__ __forceinline__ void sts_stage(float* As, float* Bs,
                                          const float4 pa[2], const float4& pb, int tid)
{
#pragma unroll
    for (int i = 0; i < 2; i++) {
        int idx = tid + i * 256;
        int r = idx >> 2, c4 = idx & 3;
        float* p = As + (c4 * 4) * AP + r;
        p[0] = pa[i].x; p[AP] = pa[i].y; p[2 * AP] = pa[i].z; p[3 * AP] = pa[i].w;
    }
    {
        int q = tid >> 2, c4 = tid & 3;
        float* p = Bs + (c4 * 4) * AP + 2 * q;
        p[0] = pb.x;          p[1] = pb.x;
        p[AP] = pb.y;         p[AP + 1] = pb.y;
        p[2 * AP] = pb.z;     p[2 * AP + 1] = pb.z;
        p[3 * AP] = pb.w;     p[3 * AP + 1] = pb.w;
    }
}
__device__ __forceinline__ void gemm128x64(const float* __restrict__ A,
                                           const float* __restrict__ Bm,
                                           int kbeg, int kend,
                                           float* As, float* Bs,
                                           unsigned long long c2[2][8])
{
    const int tid = threadIdx.x;
    const int w = tid >> 5, l = tid & 31;
#pragma unroll
    for (int p = 0; p < 2; p++)
#pragma unroll
        for (int c = 0; c < 8; c++) c2[p][c] = 0ull;

    float4 pa[2]; float4 pb;
    ldg_stage(A, Bm, kbeg, pa, pb, tid);
    sts_stage(As, Bs, pa, pb, tid);
    __syncthreads();

    const int ns = (kend - kbeg) >> 4;
    for (int s = 0; s < ns; s++) {
        const float* Ac = As + (s & 1) * STG;
        const float* Bc = Bs + (s & 1) * STG;
        if (s + 1 < ns) ldg_stage(A, Bm, kbeg + (s + 1) * KC, pa, pb, tid);
#pragma unroll
        for (int k = 0; k < KC; k++) {
            ulonglong2 a = *(const ulonglong2*)(Ac + k * AP + 4 * l);
            const float* bp = Bc + k * AP + 16 * w;
            ulonglong2 b0 = *(const ulonglong2*)(bp);
            ulonglong2 b1 = *(const ulonglong2*)(bp + 4);
            ulonglong2 b2 = *(const ulonglong2*)(bp + 8);
            ulonglong2 b3 = *(const ulonglong2*)(bp + 12);
            c2[0][0] = f32x2_fma(a.x, b0.x, c2[0][0]);
            c2[0][1] = f32x2_fma(a.x, b0.y, c2[0][1]);
            c2[0][2] = f32x2_fma(a.x, b1.x, c2[0][2]);
            c2[0][3] = f32x2_fma(a.x, b1.y, c2[0][3]);
            c2[0][4] = f32x2_fma(a.x, b2.x, c2[0][4]);
            c2[0][5] = f32x2_fma(a.x, b2.y, c2[0][5]);
            c2[0][6] = f32x2_fma(a.x, b3.x, c2[0][6]);
            c2[0][7] = f32x2_fma(a.x, b3.y, c2[0][7]);
            c2[1][0] = f32x2_fma(a.y, b0.x, c2[1][0]);
            c2[1][1] = f32x2_fma(a.y, b0.y, c2[1][1]);
            c2[1][2] = f32x2_fma(a.y, b1.x, c2[1][2]);
            c2[1][3] = f32x2_fma(a.y, b1.y, c2[1][3]);
            c2[1][4] = f32x2_fma(a.y, b2.x, c2[1][4]);
            c2[1][5] = f32x2_fma(a.y, b2.y, c2[1][5]);
            c2[1][6] = f32x2_fma(a.y, b3.x, c2[1][6]);
            c2[1][7] = f32x2_fma(a.y, b3.y, c2[1][7]);
        }
        if (s + 1 < ns) {
            sts_stage(As + ((s + 1) & 1) * STG, Bs + ((s + 1) & 1) * STG, pa, pb, tid);
            __syncthreads();
        }
    }
}

// ---------------- 1) QW split-K partials ----------------
__global__ void __launch_bounds__(256, 2) qw_kernel(const float* __restrict__ kw,
                                                    const float* __restrict__ qe)
{
    __shared__ float As[2 * STG];
    __shared__ float Bs[2 * STG];
    const int d0 = blockIdx.x * 128;
    const int kc = blockIdx.y;
    unsigned long long c2[2][8];
    gemm128x64(kw + (size_t)d0 * kD, qe, kc * 64, kc * 64 + 64, As, Bs, c2);

    const int tid = threadIdx.x, w = tid >> 5, l = tid & 31;
    const int dbase = d0 + 4 * l;
    float* gp = g_QWp + (size_t)kc * (kNQ * kD);
#pragma unroll
    for (int c = 0; c < 8; c++) {
        const int q = 8 * w + c;
        float4 o;
        f32x2_unpack(c2[0][c], o.x, o.y);
        f32x2_unpack(c2[1][c], o.z, o.w);
        *(float4*)(gp + (size_t)q * kD + dbase) = o;
    }
}

// ---------------- 1b) reduce partials, scale 1/32 ----------------
__global__ void __launch_bounds__(256) qwred_kernel()
{
    const int i4 = blockIdx.x * 256 + threadIdx.x;
    float4 acc = make_float4(0.f, 0.f, 0.f, 0.f);
#pragma unroll
    for (int c = 0; c < kSPLIT; c++) {
        float4 v = ((const float4*)g_QWp)[(size_t)c * 16384 + i4];
        acc.x += v.x; acc.y += v.y; acc.z += v.z; acc.w += v.w;
    }
    acc.x *= 0.03125f; acc.y *= 0.03125f; acc.z *= 0.03125f; acc.w *= 0.03125f;
    ((float4*)g_QW)[i4] = acc;
}

// ---------------- 2) qb = (query_embed @ key_b)/32 ----------------
__global__ void qb_kernel(const float* __restrict__ qe, const float* __restrict__ kb)
{
    const int q = threadIdx.x;            // 64 threads
    const float* row = qe + (size_t)q * kD;
    float s0 = 0.f, s1 = 0.f, s2 = 0.f, s3 = 0.f;
    for (int h = 0; h < kD; h += 4) {
        s0 = fmaf(row[h + 0], kb[h + 0], s0);
        s1 = fmaf(row[h + 1], kb[h + 1], s1);
        s2 = fmaf(row[h + 2], kb[h + 2], s2);
        s3 = fmaf(row[h + 3], kb[h + 3], s3);
    }
    g_qb[q] = ((s0 + s1) + (s2 + s3)) * 0.03125f;
}

// ---------------- 3) scores (128 thr, 8x8 tile) + fused density ----------------
__global__ void __launch_bounds__(128) scores_kernel(
    const float* __restrict__ tf, const float* __restrict__ den,
    const float* __restrict__ w1, const float* __restrict__ b1,
    const float* __restrict__ w2, const float* __restrict__ b2)
{
    __shared__ float sm[SMEM_FLOATS];
    float* Asm = sm;                       // 2 * ASTG
    float* Bsm = sm + 2 * ASTG;            // 2 * BSTG
    const int tid = threadIdx.x;
    const int r = tid >> 3;                // 0..15 -> rows 8r..8r+7
    const int c = tid & 7;                 // 0..7  -> cols 8c..8c+7
    const int b = blockIdx.y;
    const int n0 = blockIdx.x * 128;
    const float* A = tf + ((size_t)b * kN + n0) * kD;

    unsigned long long acc[4][8];
#pragma unroll
    for (int p = 0; p < 4; p++)
#pragma unroll
        for (int j = 0; j < 8; j++) acc[p][j] = 0ull;

    float4 pa[4]; float4 pb[2];
    auto LDG = [&](int k0) {
#pragma unroll
        for (int i = 0; i < 4; i++) {          // A: 512 float4 / 128 thr
            int idx = tid + i * 128;
            int ar = idx >> 2, ac4 = idx & 3;
            pa[i] = *(const float4*)(A + (size_t)ar * kD + k0 + ac4 * 4);
        }
#pragma unroll
        for (int i = 0; i < 2; i++) {          // B: 256 float4 / 128 thr
            int idx = tid + i * 128;
            int q = idx >> 2, qc4 = idx & 3;
            pb[i] = *(const float4*)(g_QW + (size_t)q * kD + k0 + qc4 * 4);
        }
    };
    auto STS = [&](int st) {
        float* As = Asm + st * ASTG;
        float* Bs = Bsm + st * BSTG;
#pragma unroll
        for (int i = 0; i < 4; i++) {          // A transposed, pitch AP3
            int idx = tid + i * 128;
            int ar = idx >> 2, ac4 = idx & 3;
            float* p = As + (ac4 * 4) * AP3 + ar;
            p[0] = pa[i].x; p[AP3] = pa[i].y; p[2 * AP3] = pa[i].z; p[3 * AP3] = pa[i].w;
        }
#pragma unroll
        for (int i = 0; i < 2; i++) {          // B dup chunks: chunk (jj>>1)*8 + (q>>3)
            int idx = tid + i * 128;
            int q = idx >> 2, qc4 = idx & 3;
            const int off = ((q & 7) >> 1) * 32 + (q >> 3) * 4 + (q & 1) * 2;
            float v[4] = {pb[i].x, pb[i].y, pb[i].z, pb[i].w};
#pragma unroll
            for (int e = 0; e < 4; e++) {
                float* p = Bs + (qc4 * 4 + e) * BP3 + off;
                p[0] = v[e]; p[1] = v[e];
            }
        }
    };

    LDG(0);
    STS(0);
    __syncthreads();

    for (int s = 0; s < 64; s++) {
        const float* Ac = Asm + (s & 1) * ASTG;
        const float* Bc = Bsm + (s & 1) * BSTG;
        if (s + 1 < 64) LDG((s + 1) * KC3);
#pragma unroll
        for (int k = 0; k < KC3; k++) {
            ulonglong2 a01 = *(const ulonglong2*)(Ac + k * AP3 + 8 * r);
            ulonglong2 a23 = *(const ulonglong2*)(Ac + k * AP3 + 8 * r + 4);
            ulonglong2 bb0 = *(const ulonglong2*)(Bc + k * BP3 + (0 * 8 + c) * 4);
            ulonglong2 bb1 = *(const ulonglong2*)(Bc + k * BP3 + (1 * 8 + c) * 4);
            ulonglong2 bb2 = *(const ulonglong2*)(Bc + k * BP3 + (2 * 8 + c) * 4);
            ulonglong2 bb3 = *(const ulonglong2*)(Bc + k * BP3 + (3 * 8 + c) * 4);
            unsigned long long av[4] = {a01.x, a01.y, a23.x, a23.y};
#pragma unroll
            for (int p = 0; p < 4; p++) {
                acc[p][0] = f32x2_fma(av[p], bb0.x, acc[p][0]);
                acc[p][1] = f32x2_fma(av[p], bb0.y, acc[p][1]);
                acc[p][2] = f32x2_fma(av[p], bb1.x, acc[p][2]);
                acc[p][3] = f32x2_fma(av[p], bb1.y, acc[p][3]);
                acc[p][4] = f32x2_fma(av[p], bb2.x, acc[p][4]);
                acc[p][5] = f32x2_fma(av[p], bb2.y, acc[p][5]);
                acc[p][6] = f32x2_fma(av[p], bb3.x, acc[p][6]);
                acc[p][7] = f32x2_fma(av[p], bb3.y, acc[p][7]);
            }
        }
        if (s + 1 < 64) {
            STS((s + 1) & 1);
            __syncthreads();
        }
    }
    __syncthreads();   // all reads of GEMM smem done before reuse

    // ---- fused density (1 thread/token, broadcast reads; r2-proven pattern) ----
    float4* wbuf = (float4*)sm;   // [0:512) w1, [512:1024) b1, [1024:1536) w2
    for (int i = tid; i < 512; i += 128) {
        wbuf[i]        = ((const float4*)w1)[i];
        wbuf[512 + i]  = ((const float4*)b1)[i];
        wbuf[1024 + i] = ((const float4*)w2)[i];
    }
    __syncthreads();

    const float d = den[b * kN + n0 + tid];
    float a0 = 0.f, a1 = 0.f, a2 = 0.f, a3 = 0.f;
#pragma unroll 4
    for (int j = 0; j < 512; j++) {
        float4 ww = wbuf[j], bbv = wbuf[512 + j], vv = wbuf[1024 + j];
        float h0 = fmaxf(fmaf(d, ww.x, bbv.x), 0.f);
        float h1 = fmaxf(fmaf(d, ww.y, bbv.y), 0.f);
        float h2 = fmaxf(fmaf(d, ww.z, bbv.z), 0.f);
        float h3 = fmaxf(fmaf(d, ww.w, bbv.w), 0.f);
        a0 = fmaf(h0, vv.x, a0);
        a1 = fmaf(h1, vv.y, a1);
        a2 = fmaf(h2, vv.z, a2);
        a3 = fmaf(h3, vv.w, a3);
    }
    __syncthreads();               // wbuf reads done before bias overwrite
    float* biasS = sm;             // 128 floats
    biasS[tid] = (a0 + a1) + (a2 + a3) + b2[0];
    __syncthreads();

    // ---- epilogue: S = gemm + qb + bias ----
    float qv[8];
    *(float4*)(qv)     = ((const float4*)g_qb)[2 * c];
    *(float4*)(qv + 4) = ((const float4*)g_qb)[2 * c + 1];
    float bv[8];
    *(float4*)(bv)     = *(const float4*)(biasS + 8 * r);
    *(float4*)(bv + 4) = *(const float4*)(biasS + 8 * r + 4);

#pragma unroll
    for (int j = 0; j < 8; j++) {
        const int q = 8 * c + j;
        float o[8];
#pragma unroll
        for (int p = 0; p < 4; p++)
            f32x2_unpack(acc[p][j], o[2 * p], o[2 * p + 1]);
        float4 lo, hi;
        lo.x = o[0] + qv[j] + bv[0];
        lo.y = o[1] + qv[j] + bv[1];
        lo.z = o[2] + qv[j] + bv[2];
        lo.w = o[3] + qv[j] + bv[3];
        hi.x = o[4] + qv[j] + bv[4];
        hi.y = o[5] + qv[j] + bv[5];
        hi.z = o[6] + qv[j] + bv[6];
        hi.w = o[7] + qv[j] + bv[7];
        float* outp = g_S + ((size_t)(b * kNQ + q)) * kN + n0 + 8 * r;
        *(float4*)outp = lo;
        *(float4*)(outp + 4) = hi;
    }
}

// ---------------- 4) per-(b,q) logsumexp over n ----------------
__global__ void __launch_bounds__(256) lse_kernel()
{
    const int row = blockIdx.x;           // 0..511
    const float4* s4 = (const float4*)(g_S + (size_t)row * kN);
    const int tid = threadIdx.x;
    __shared__ float red[8];

    float m = -3.402823466e38f;
    for (int i = tid; i < kN / 4; i += 256) {
        float4 v = s4[i];
        m = fmaxf(m, fmaxf(fmaxf(v.x, v.y), fmaxf(v.z, v.w)));
    }
#pragma unroll
    for (int o = 16; o; o >>= 1) m = fmaxf(m, __shfl_xor_sync(0xffffffffu, m, o));
    if ((tid & 31) == 0) red[tid >> 5] = m;
    __syncthreads();
    float mm = red[0];
#pragma unroll
    for (int i = 1; i < 8; i++) mm = fmaxf(mm, red[i]);
    __syncthreads();

    float sum = 0.f;
    for (int i = tid; i < kN / 4; i += 256) {
        float4 v = s4[i];
        sum += __expf(v.x - mm) + __expf(v.y - mm) + __expf(v.z - mm) + __expf(v.w - mm);
    }
#pragma unroll
    for (int o = 16; o; o >>= 1) sum += __shfl_xor_sync(0xffffffffu, sum, o);
    if ((tid & 31) == 0) red[tid >> 5] = sum;
    __syncthreads();
    if (tid == 0) {
        float tot = red[0];
        for (int i = 1; i < 8; i++) tot += red[i];
        g_lse[row] = mm + logf(tot);
    }
}

// ---------------- 5) importance logit = max_q (s - lse) ----------------
__global__ void __launch_bounds__(256) logit_kernel()
{
    __shared__ float ls[kNQ];
    const int tid = threadIdx.x;
    const int b = blockIdx.y;
    if (tid < kNQ) ls[tid] = g_lse[b * kNQ + tid];
    __syncthreads();
    const int n = blockIdx.x * 256 + tid;
    const float* s = g_S + (size_t)b * kNQ * kN + n;
    float best = -3.402823466e38f;
#pragma unroll 8
    for (int q = 0; q < kNQ; q++)
        best = fmaxf(best, s[(size_t)q * kN] - ls[q]);
    g_logit[b * kN + n] = best;
}

// ---------------- 6) top-1024 radix select + tie-aware compaction ----------------
__global__ void __launch_bounds__(1024) topk_kernel()
{
    const int b = blockIdx.x;
    const int tid = threadIdx.x;
    __shared__ unsigned su[kN];
    __shared__ int hist[256];
    __shared__ int sc[256];
    __shared__ int s_need, s_digit;
    __shared__ int wsum[32];
    const float* lg = g_logit + b * kN;

    for (int i = tid; i < kN; i += 1024) {
        unsigned x = __float_as_uint(lg[i]);
        su[i] = (x & 0x80000000u) ? ~x : (x ^ 0x80000000u);
    }
    if (tid == 0) s_need = kTOPK;

    unsigned prefix = 0, pmask = 0;
    for (int pass = 0; pass < 4; pass++) {
        const int shift = 24 - 8 * pass;
        if (tid < 256) hist[tid] = 0;
        __syncthreads();
        const int need = s_need;
        for (int i = tid; i < kN; i += 1024) {
            unsigned u = su[i];
            if ((u & pmask) == prefix) atomicAdd(&hist[(u >> shift) & 255], 1);
        }
        __syncthreads();
        if (tid < 256) sc[tid] = hist[255 - tid];
        __syncthreads();
        for (int off = 1; off < 256; off <<= 1) {
            int v = 0;
            if (tid < 256 && tid >= off) v = sc[tid - off];
            __syncthreads();
            if (tid < 256) sc[tid] += v;
            __syncthreads();
        }
        if (tid < 256) {
            int incl = sc[tid];
            int excl = (tid == 0) ? 0 : sc[tid - 1];
            if (incl >= need && excl < need) {
                s_digit = 255 - tid;
                s_need = need - excl;
            }
        }
        __syncthreads();
        prefix |= ((unsigned)s_digit) << shift;
        pmask |= 0xFFu << shift;
        __syncthreads();
    }
    const unsigned ut = prefix;
    const float thr = __uint_as_float((ut & 0x80000000u) ? (ut ^ 0x80000000u) : ~ut);

    float v[4];
    int gt = 0, eq = 0;
#pragma unroll
    for (int u = 0; u < 4; u++) {
        v[u] = lg[tid * 4 + u];
        gt += (v[u] > thr);
        eq += (v[u] == thr);
    }
    int x = (gt << 16) | eq;
    const int lane = tid & 31, wid = tid >> 5;
#pragma unroll
    for (int o = 1; o < 32; o <<= 1) {
        int y = __shfl_up_sync(0xffffffffu, x, o);
        if (lane >= o) x += y;
    }
    if (lane == 31) wsum[wid] = x;
    __syncthreads();
    if (wid == 0) {
        int y = wsum[lane];
#pragma unroll
        for (int o = 1; o < 32; o <<= 1) {
            int z = __shfl_up_sync(0xffffffffu, y, o);
            if (lane >= o) y += z;
        }
        wsum[lane] = y;
    }
    __syncthreads();
    const int warpbase = (wid == 0) ? 0 : wsum[wid - 1];
    const int incl = warpbase + x;
    int gt_before = (incl >> 16) - gt;
    int eq_before = (incl & 0xffff) - eq;
    const int total_gt = wsum[31] >> 16;
    const int need_eq = kTOPK - total_gt;
    int* outi = g_idx + b * kTOPK;
#pragma unroll
    for (int u = 0; u < 4; u++) {
        const int n = tid * 4 + u;
        if (v[u] > thr) {
            int pos = gt_before + min(eq_before, need_eq);
            outi[pos] = n;
            gt_before++;
        } else if (v[u] == thr) {
            if (eq_before < need_eq) outi[gt_before + eq_before] = n;
            eq_before++;
        }
    }
}

// ---------------- 7) gather selected rows ----------------
__global__ void __launch_bounds__(256) gather_kernel(const float* __restrict__ tf,
                                                     float* __restrict__ out)
{
    const int b = blockIdx.y, k = blockIdx.x;
    const int row = g_idx[b * kTOPK + k];
    const float4* src = (const float4*)(tf + ((size_t)b * kN + row) * kD);
    float4* dst = (float4*)(out + ((size_t)b * kTOPK + k) * kD);
    dst[threadIdx.x] = src[threadIdx.x];
}

// ---------------- launch ----------------
extern "C" void kernel_launch(void* const* d_in, const int* in_sizes, int n_in,
                              void* d_out, int out_size)
{
    (void)in_sizes; (void)n_in; (void)out_size;
    const float* tf  = (const float*)d_in[0];   // token_features  [8,4096,1024]
    const float* den = (const float*)d_in[1];   // token_densities [8,4096]
    const float* qe  = (const float*)d_in[2];   // query_embed     [64,1024]
    const float* kw  = (const float*)d_in[3];   // key_w           [1024,1024]
    const float* kb  = (const float*)d_in[4];   // key_b           [1024]
    const float* w1  = (const float*)d_in[5];   // de_w1           [1,2048]
    const float* b1  = (const float*)d_in[6];   // de_b1           [2048]
    const float* w2  = (const float*)d_in[7];   // de_w2           [2048,1]
    const float* b2  = (const float*)d_in[8];   // de_b2           [1]
    float* out = (float*)d_out;                 // [8,1024,1024] f32

    qw_kernel<<<dim3(kD / 128, kSPLIT), 256>>>(kw, qe);
    qwred_kernel<<<64, 256>>>();
    qb_kernel<<<1, 64>>>(qe, kb);
    scores_kernel<<<dim3(kN / 128, kB), 128>>>(tf, den, w1, b1, w2, b2);
    lse_kernel<<<kB * kNQ, 256>>>();
    logit_kernel<<<dim3(kN / 256, kB), 256>>>();
    topk_kernel<<<kB, 1024>>>();
    gather_kernel<<<dim3(kTOPK, kB), 256>>>(tf, out);
}

// round 15
// speedup vs baseline: 1.1855x; 1.1855x over previous
#include <cuda_runtime.h>
#include <cstdint>

constexpr int kB = 8, kN = 4096, kD = 1024, kNQ = 64;
constexpr int kTOPK = 1024;
constexpr int KC = 16;      // K-chunk per smem stage
constexpr int AP = 132;     // smem pitch (floats)
constexpr int STG = KC * AP;
constexpr int kSPLIT = 16;  // qw split-K
constexpr int SMEM_TOT = 4 * STG;   // 8448 floats = 33792 B
// density overlay: wbuf = 1536 float4 = 6144 floats, bias = 128 floats -> 6272 <= 8448 OK

// ---------------- scratch ----------------
__device__ float g_QW[kNQ * kD];            // (query_embed @ key_w^T) / 32
__device__ float g_QWp[kSPLIT * kNQ * kD];  // split-K partials
__device__ float g_qb[kNQ];                 // (query_embed @ key_b) / 32
__device__ float g_S[(size_t)kB * kNQ * kN];// scores [b][q][n]
__device__ float g_lse[kB * kNQ];           // logsumexp per (b,q)
__device__ float g_logit[kB * kN];          // max_q (s - lse) per token
__device__ int   g_idx[kB * kTOPK];         // selected indices, ascending

// ---------------- f32x2 helpers ----------------
__device__ __forceinline__ void f32x2_unpack(unsigned long long v, float& lo, float& hi) {
    asm("mov.b64 {%0, %1}, %2;" : "=f"(lo), "=f"(hi) : "l"(v));
}
__device__ __forceinline__ unsigned long long f32x2_fma(unsigned long long a,
                                                        unsigned long long b,
                                                        unsigned long long c) {
    unsigned long long d;
    asm("fma.rn.f32x2 %0, %1, %2, %3;" : "=l"(d) : "l"(a), "l"(b), "l"(c));
    return d;
}

// ---------------- stage loaders for the 128x64 tile GEMM ----------------
__device__ __forceinline__ void ldg_stage(const float* __restrict__ A,
                                          const float* __restrict__ Bm,
                                          int k0, float4 pa[2], float4& pb, int tid)
{
#pragma unroll
    for (int i = 0; i < 2; i++) {
        int idx = tid + i * 256;
        int r = idx >> 2, c4 = idx & 3;
        pa[i] = *(const float4*)(A + (size_t)r * kD + k0 + c4 * 4);
    }
    {
        int q = tid >> 2, c4 = tid & 3;
        pb = *(const float4*)(Bm + (size_t)q * kD + k0 + c4 * 4);
    }
}
__device__ __forceinline__ void sts_stage(float* As, float* Bs,
                                          const float4 pa[2], const float4& pb, int tid)
{
#pragma unroll
    for (int i = 0; i < 2; i++) {
        int idx = tid + i * 256;
        int r = idx >> 2, c4 = idx & 3;
        float* p = As + (c4 * 4) * AP + r;
        p[0] = pa[i].x; p[AP] = pa[i].y; p[2 * AP] = pa[i].z; p[3 * AP] = pa[i].w;
    }
    {
        int q = tid >> 2, c4 = tid & 3;
        float* p = Bs + (c4 * 4) * AP + 2 * q;
        p[0] = pb.x;          p[1] = pb.x;
        p[AP] = pb.y;         p[AP + 1] = pb.y;
        p[2 * AP] = pb.z;     p[2 * AP + 1] = pb.z;
        p[3 * AP] = pb.w;     p[3 * AP + 1] = pb.w;
    }
}

// C[r][c] = sum_{k} A[r][k]*Bm[c][k]; double-buffered, 256 thr, 4x8 tile.
__device__ __forceinline__ void gemm128x64(const float* __restrict__ A,
                                           const float* __restrict__ Bm,
                                           int kbeg, int kend,
                                           float* As, float* Bs,
                                           unsigned long long c2[2][8])
{
    const int tid = threadIdx.x;
    const int w = tid >> 5, l = tid & 31;
#pragma unroll
    for (int p = 0; p < 2; p++)
#pragma unroll
        for (int c = 0; c < 8; c++) c2[p][c] = 0ull;

    float4 pa[2]; float4 pb;
    ldg_stage(A, Bm, kbeg, pa, pb, tid);
    sts_stage(As, Bs, pa, pb, tid);
    __syncthreads();

    const int ns = (kend - kbeg) >> 4;
    for (int s = 0; s < ns; s++) {
        const float* Ac = As + (s & 1) * STG;
        const float* Bc = Bs + (s & 1) * STG;
        if (s + 1 < ns) ldg_stage(A, Bm, kbeg + (s + 1) * KC, pa, pb, tid);
#pragma unroll
        for (int k = 0; k < KC; k++) {
            ulonglong2 a = *(const ulonglong2*)(Ac + k * AP + 4 * l);
            const float* bp = Bc + k * AP + 16 * w;
            ulonglong2 b0 = *(const ulonglong2*)(bp);
            ulonglong2 b1 = *(const ulonglong2*)(bp + 4);
            ulonglong2 b2 = *(const ulonglong2*)(bp + 8);
            ulonglong2 b3 = *(const ulonglong2*)(bp + 12);
            c2[0][0] = f32x2_fma(a.x, b0.x, c2[0][0]);
            c2[0][1] = f32x2_fma(a.x, b0.y, c2[0][1]);
            c2[0][2] = f32x2_fma(a.x, b1.x, c2[0][2]);
            c2[0][3] = f32x2_fma(a.x, b1.y, c2[0][3]);
            c2[0][4] = f32x2_fma(a.x, b2.x, c2[0][4]);
            c2[0][5] = f32x2_fma(a.x, b2.y, c2[0][5]);
            c2[0][6] = f32x2_fma(a.x, b3.x, c2[0][6]);
            c2[0][7] = f32x2_fma(a.x, b3.y, c2[0][7]);
            c2[1][0] = f32x2_fma(a.y, b0.x, c2[1][0]);
            c2[1][1] = f32x2_fma(a.y, b0.y, c2[1][1]);
            c2[1][2] = f32x2_fma(a.y, b1.x, c2[1][2]);
            c2[1][3] = f32x2_fma(a.y, b1.y, c2[1][3]);
            c2[1][4] = f32x2_fma(a.y, b2.x, c2[1][4]);
            c2[1][5] = f32x2_fma(a.y, b2.y, c2[1][5]);
            c2[1][6] = f32x2_fma(a.y, b3.x, c2[1][6]);
            c2[1][7] = f32x2_fma(a.y, b3.y, c2[1][7]);
        }
        if (s + 1 < ns) {
            sts_stage(As + ((s + 1) & 1) * STG, Bs + ((s + 1) & 1) * STG, pa, pb, tid);
            __syncthreads();
        }
    }
}

// ---------------- 1) QW split-K partials ----------------
__global__ void __launch_bounds__(256, 2) qw_kernel(const float* __restrict__ kw,
                                                    const float* __restrict__ qe)
{
    __shared__ float sm[SMEM_TOT];
    const int d0 = blockIdx.x * 128;
    const int kc = blockIdx.y;
    unsigned long long c2[2][8];
    gemm128x64(kw + (size_t)d0 * kD, qe, kc * 64, kc * 64 + 64, sm, sm + 2 * STG, c2);

    const int tid = threadIdx.x, w = tid >> 5, l = tid & 31;
    const int dbase = d0 + 4 * l;
    float* gp = g_QWp + (size_t)kc * (kNQ * kD);
#pragma unroll
    for (int c = 0; c < 8; c++) {
        const int q = 8 * w + c;
        float4 o;
        f32x2_unpack(c2[0][c], o.x, o.y);
        f32x2_unpack(c2[1][c], o.z, o.w);
        *(float4*)(gp + (size_t)q * kD + dbase) = o;
    }
}

// ---------------- 1b) reduce partials + qb (block 0) ----------------
__global__ void __launch_bounds__(256) qwred_kernel(const float* __restrict__ qe,
                                                    const float* __restrict__ kb)
{
    const int tid = threadIdx.x;
    const int i4 = blockIdx.x * 256 + tid;
    float4 acc = make_float4(0.f, 0.f, 0.f, 0.f);
#pragma unroll
    for (int c = 0; c < kSPLIT; c++) {
        float4 v = ((const float4*)g_QWp)[(size_t)c * 16384 + i4];
        acc.x += v.x; acc.y += v.y; acc.z += v.z; acc.w += v.w;
    }
    acc.x *= 0.03125f; acc.y *= 0.03125f; acc.z *= 0.03125f; acc.w *= 0.03125f;
    ((float4*)g_QW)[i4] = acc;

    if (blockIdx.x == 0 && tid < kNQ) {       // fused qb
        const float* row = qe + (size_t)tid * kD;
        float s0 = 0.f, s1 = 0.f, s2 = 0.f, s3 = 0.f;
        for (int h = 0; h < kD; h += 4) {
            s0 = fmaf(row[h + 0], kb[h + 0], s0);
            s1 = fmaf(row[h + 1], kb[h + 1], s1);
            s2 = fmaf(row[h + 2], kb[h + 2], s2);
            s3 = fmaf(row[h + 3], kb[h + 3], s3);
        }
        g_qb[tid] = ((s0 + s1) + (s2 + s3)) * 0.03125f;
    }
}

// ---------------- 2) scores + fused density ----------------
__global__ void __launch_bounds__(256, 2) scores_kernel(
    const float* __restrict__ tf, const float* __restrict__ den,
    const float* __restrict__ w1, const float* __restrict__ b1,
    const float* __restrict__ w2, const float* __restrict__ b2)
{
    __shared__ float sm[SMEM_TOT];            // 8448 floats
    const int b = blockIdx.y;
    const int n0 = blockIdx.x * 128;
    unsigned long long c2[2][8];
    gemm128x64(tf + ((size_t)b * kN + n0) * kD, g_QW, 0, kD, sm, sm + 2 * STG, c2);
    __syncthreads();   // all smem reads of last stage done before reuse

    const int tid = threadIdx.x, w = tid >> 5, l = tid & 31;

    // ---- fused density: wbuf = 6144 floats at sm[0], bias at sm[6144] ----
    float4* wbuf = (float4*)sm;   // [0:512) w1, [512:1024) b1, [1024:1536) w2
    for (int i = tid; i < 512; i += 256) {
        wbuf[i]        = ((const float4*)w1)[i];
        wbuf[512 + i]  = ((const float4*)b1)[i];
        wbuf[1024 + i] = ((const float4*)w2)[i];
    }
    __syncthreads();

    const int tok = tid >> 1, sub = tid & 1;      // 2 threads per token
    const float d = den[b * kN + n0 + tok];
    float a0 = 0.f, a1 = 0.f, a2 = 0.f, a3 = 0.f;
#pragma unroll 4
    for (int i = 0; i < 256; i++) {
        const int j = 2 * i + sub;                // parity split: adjacent addrs
        float4 ww = wbuf[j], bbv = wbuf[512 + j], vv = wbuf[1024 + j];
        float h0 = fmaxf(fmaf(d, ww.x, bbv.x), 0.f);
        float h1 = fmaxf(fmaf(d, ww.y, bbv.y), 0.f);
        float h2 = fmaxf(fmaf(d, ww.z, bbv.z), 0.f);
        float h3 = fmaxf(fmaf(d, ww.w, bbv.w), 0.f);
        a0 = fmaf(h0, vv.x, a0);
        a1 = fmaf(h1, vv.y, a1);
        a2 = fmaf(h2, vv.z, a2);
        a3 = fmaf(h3, vv.w, a3);
    }
    float bsum = (a0 + a1) + (a2 + a3);
    bsum += __shfl_xor_sync(0xffffffffu, bsum, 1);
    float* biasS = sm + 6144;                     // 128 floats, disjoint from wbuf
    if (sub == 0) biasS[tok] = bsum + b2[0];
    __syncthreads();

    // ---- epilogue: S = gemm + qb + bias ----
    const int nbase = n0 + 4 * l;
    const float4 bvv = *(const float4*)(biasS + 4 * l);
#pragma unroll
    for (int c = 0; c < 8; c++) {
        const int q = 8 * w + c;
        const float add = g_qb[q];
        float4 o;
        f32x2_unpack(c2[0][c], o.x, o.y);
        f32x2_unpack(c2[1][c], o.z, o.w);
        o.x += add + bvv.x;
        o.y += add + bvv.y;
        o.z += add + bvv.z;
        o.w += add + bvv.w;
        *(float4*)(g_S + ((size_t)(b * kNQ + q)) * kN + nbase) = o;
    }
}

// ---------------- 3) per-(b,q) logsumexp over n ----------------
__global__ void __launch_bounds__(256) lse_kernel()
{
    const int row = blockIdx.x;           // 0..511
    const float4* s4 = (const float4*)(g_S + (size_t)row * kN);
    const int tid = threadIdx.x;
    __shared__ float red[8];

    float m = -3.402823466e38f;
    for (int i = tid; i < kN / 4; i += 256) {
        float4 v = s4[i];
        m = fmaxf(m, fmaxf(fmaxf(v.x, v.y), fmaxf(v.z, v.w)));
    }
#pragma unroll
    for (int o = 16; o; o >>= 1) m = fmaxf(m, __shfl_xor_sync(0xffffffffu, m, o));
    if ((tid & 31) == 0) red[tid >> 5] = m;
    __syncthreads();
    float mm = red[0];
#pragma unroll
    for (int i = 1; i < 8; i++) mm = fmaxf(mm, red[i]);
    __syncthreads();

    float sum = 0.f;
    for (int i = tid; i < kN / 4; i += 256) {
        float4 v = s4[i];
        sum += __expf(v.x - mm) + __expf(v.y - mm) + __expf(v.z - mm) + __expf(v.w - mm);
    }
#pragma unroll
    for (int o = 16; o; o >>= 1) sum += __shfl_xor_sync(0xffffffffu, sum, o);
    if ((tid & 31) == 0) red[tid >> 5] = sum;
    __syncthreads();
    if (tid == 0) {
        float tot = red[0];
        for (int i = 1; i < 8; i++) tot += red[i];
        g_lse[row] = mm + logf(tot);
    }
}

// ---------------- 4) importance logit = max_q (s - lse) ----------------
__global__ void __launch_bounds__(256) logit_kernel()
{
    __shared__ float ls[kNQ];
    const int tid = threadIdx.x;
    const int b = blockIdx.y;
    if (tid < kNQ) ls[tid] = g_lse[b * kNQ + tid];
    __syncthreads();
    const int n = blockIdx.x * 256 + tid;
    const float* s = g_S + (size_t)b * kNQ * kN + n;
    float best = -3.402823466e38f;
#pragma unroll 8
    for (int q = 0; q < kNQ; q++)
        best = fmaxf(best, s[(size_t)q * kN] - ls[q]);
    g_logit[b * kN + n] = best;
}

// ---------------- 5) top-1024 radix select + tie-aware compaction ----------------
__global__ void __launch_bounds__(1024) topk_kernel()
{
    const int b = blockIdx.x;
    const int tid = threadIdx.x;
    __shared__ unsigned su[kN];
    __shared__ int hist[256];
    __shared__ int sc[256];
    __shared__ int s_need, s_digit;
    __shared__ int wsum[32];
    const float* lg = g_logit + b * kN;

    for (int i = tid; i < kN; i += 1024) {
        unsigned x = __float_as_uint(lg[i]);
        su[i] = (x & 0x80000000u) ? ~x : (x ^ 0x80000000u);
    }
    if (tid == 0) s_need = kTOPK;

    unsigned prefix = 0, pmask = 0;
    for (int pass = 0; pass < 4; pass++) {
        const int shift = 24 - 8 * pass;
        if (tid < 256) hist[tid] = 0;
        __syncthreads();
        const int need = s_need;
        for (int i = tid; i < kN; i += 1024) {
            unsigned u = su[i];
            if ((u & pmask) == prefix) atomicAdd(&hist[(u >> shift) & 255], 1);
        }
        __syncthreads();
        if (tid < 256) sc[tid] = hist[255 - tid];
        __syncthreads();
        for (int off = 1; off < 256; off <<= 1) {
            int v = 0;
            if (tid < 256 && tid >= off) v = sc[tid - off];
            __syncthreads();
            if (tid < 256) sc[tid] += v;
            __syncthreads();
        }
        if (tid < 256) {
            int incl = sc[tid];
            int excl = (tid == 0) ? 0 : sc[tid - 1];
            if (incl >= need && excl < need) {
                s_digit = 255 - tid;
                s_need = need - excl;
            }
        }
        __syncthreads();
        prefix |= ((unsigned)s_digit) << shift;
        pmask |= 0xFFu << shift;
        __syncthreads();
    }
    const unsigned ut = prefix;
    const float thr = __uint_as_float((ut & 0x80000000u) ? (ut ^ 0x80000000u) : ~ut);

    float v[4];
    int gt = 0, eq = 0;
#pragma unroll
    for (int u = 0; u < 4; u++) {
        v[u] = lg[tid * 4 + u];
        gt += (v[u] > thr);
        eq += (v[u] == thr);
    }
    int x = (gt << 16) | eq;
    const int lane = tid & 31, wid = tid >> 5;
#pragma unroll
    for (int o = 1; o < 32; o <<= 1) {
        int y = __shfl_up_sync(0xffffffffu, x, o);
        if (lane >= o) x += y;
    }
    if (lane == 31) wsum[wid] = x;
    __syncthreads();
    if (wid == 0) {
        int y = wsum[lane];
#pragma unroll
        for (int o = 1; o < 32; o <<= 1) {
            int z = __shfl_up_sync(0xffffffffu, y, o);
            if (lane >= o) y += z;
        }
        wsum[lane] = y;
    }
    __syncthreads();
    const int warpbase = (wid == 0) ? 0 : wsum[wid - 1];
    const int incl = warpbase + x;
    int gt_before = (incl >> 16) - gt;
    int eq_before = (incl & 0xffff) - eq;
    const int total_gt = wsum[31] >> 16;
    const int need_eq = kTOPK - total_gt;
    int* outi = g_idx + b * kTOPK;
#pragma unroll
    for (int u = 0; u < 4; u++) {
        const int n = tid * 4 + u;
        if (v[u] > thr) {
            int pos = gt_before + min(eq_before, need_eq);
            outi[pos] = n;
            gt_before++;
        } else if (v[u] == thr) {
            if (eq_before < need_eq) outi[gt_before + eq_before] = n;
            eq_before++;
        }
    }
}

// ---------------- 6) gather selected rows ----------------
__global__ void __launch_bounds__(256) gather_kernel(const float* __restrict__ tf,
                                                     float* __restrict__ out)
{
    const int b = blockIdx.y, k = blockIdx.x;
    const int row = g_idx[b * kTOPK + k];
    const float4* src = (const float4*)(tf + ((size_t)b * kN + row) * kD);
    float4* dst = (float4*)(out + ((size_t)b * kTOPK + k) * kD);
    dst[threadIdx.x] = src[threadIdx.x];
}

// ---------------- launch ----------------
extern "C" void kernel_launch(void* const* d_in, const int* in_sizes, int n_in,
                              void* d_out, int out_size)
{
    (void)in_sizes; (void)n_in; (void)out_size;
    const float* tf  = (const float*)d_in[0];   // token_features  [8,4096,1024]
    const float* den = (const float*)d_in[1];   // token_densities [8,4096]
    const float* qe  = (const float*)d_in[2];   // query_embed     [64,1024]
    const float* kw  = (const float*)d_in[3];   // key_w           [1024,1024]
    const float* kb  = (const float*)d_in[4];   // key_b           [1024]
    const float* w1  = (const float*)d_in[5];   // de_w1           [1,2048]
    const float* b1  = (const float*)d_in[6];   // de_b1           [2048]
    const float* w2  = (const float*)d_in[7];   // de_w2           [2048,1]
    const float* b2  = (const float*)d_in[8];   // de_b2           [1]
    float* out = (float*)d_out;                 // [8,1024,1024] f32

    qw_kernel<<<dim3(kD / 128, kSPLIT), 256>>>(kw, qe);
    qwred_kernel<<<64, 256>>>(qe, kb);
    scores_kernel<<<dim3(kN / 128, kB), 256>>>(tf, den, w1, b1, w2, b2);
    lse_kernel<<<kB * kNQ, 256>>>();
    logit_kernel<<<dim3(kN / 256, kB), 256>>>();
    topk_kernel<<<kB, 1024>>>();
    gather_kernel<<<dim3(kTOPK, kB), 256>>>(tf, out);
}